// round 2
// baseline (speedup 1.0000x reference)
#include <cuda_runtime.h>

// Problem constants
#define BB 64
#define TT 512
#define II 512
#define HH 1024
#define GG 4096   // 4*H

// ---------------------------------------------------------------------------
// Device scratch (static: no allocations allowed in kernel_launch)
// g_xp[s][b][dir*4096 + g] : input projection (+ biases) at ACTUAL time s.
//   fw step t reads s = t; bw step t reads s = T-1-t.
// g_h: hidden state, double-buffered by step parity (cross-block RAW hazard).
// g_c: cell state, single-buffered (each block owns its hidden-unit slice).
// ---------------------------------------------------------------------------
__device__ float g_xp[TT][BB][2 * GG];      // 1 GB
__device__ float g_h[2][2][BB][HH];         // [parity][dir][b][k]
__device__ float g_c[2][BB][HH];            // [dir][b][k]

// ---------------------------------------------------------------------------
// Zero h (both parities) and c — must run every launch (determinism).
// ---------------------------------------------------------------------------
__global__ void init_state() {
    int idx = blockIdx.x * blockDim.x + threadIdx.x;
    const int n_h = 2 * 2 * BB * HH;
    const int n_c = 2 * BB * HH;
    if (idx < n_h) ((float*)g_h)[idx] = 0.f;
    if (idx < n_c) ((float*)g_c)[idx] = 0.f;
}

// ---------------------------------------------------------------------------
// xp GEMM: g_xp[s][b][dir*4096+n] = sum_i x[b][s][i] * w_ih[dir][n][i] + bias
// Tiled fp32 SGEMM: 128x128 tile, BK=16, 256 threads, 8x8 per thread.
// M = T*B = 32768 (m = s*64 + b), N = 4096 per dir (grid.z), K = 512.
// ---------------------------------------------------------------------------
__global__ __launch_bounds__(256) void xp_gemm(
    const float* __restrict__ x,
    const float* __restrict__ w_fw, const float* __restrict__ w_bw,
    const float* __restrict__ bih_fw, const float* __restrict__ bhh_fw,
    const float* __restrict__ bih_bw, const float* __restrict__ bhh_bw)
{
    const int dir = blockIdx.z;
    const float* __restrict__ w  = dir ? w_bw  : w_fw;
    const float* __restrict__ bi = dir ? bih_bw : bih_fw;
    const float* __restrict__ bh = dir ? bhh_bw : bhh_fw;
    const int n0 = blockIdx.x * 128;
    const int m0 = blockIdx.y * 128;

    __shared__ float As[16][128];
    __shared__ float Bs[16][128];

    const int tid = threadIdx.x;
    const int tx = tid & 15;
    const int ty = tid >> 4;

    float acc[8][8];
    #pragma unroll
    for (int i = 0; i < 8; i++)
        #pragma unroll
        for (int j = 0; j < 8; j++) acc[i][j] = 0.f;

    for (int k0 = 0; k0 < II; k0 += 16) {
        #pragma unroll
        for (int it = 0; it < 2; it++) {
            int idx = tid + it * 256;       // 0..511
            int row = idx >> 2;             // 0..127
            int kv  = (idx & 3) * 4;        // 0,4,8,12
            int m = m0 + row;
            int s = m >> 6;                 // m / 64
            int b = m & 63;
            float4 va = *reinterpret_cast<const float4*>(
                x + ((size_t)b * TT + s) * II + k0 + kv);
            As[kv + 0][row] = va.x; As[kv + 1][row] = va.y;
            As[kv + 2][row] = va.z; As[kv + 3][row] = va.w;
            float4 vb = *reinterpret_cast<const float4*>(
                w + (size_t)(n0 + row) * II + k0 + kv);
            Bs[kv + 0][row] = vb.x; Bs[kv + 1][row] = vb.y;
            Bs[kv + 2][row] = vb.z; Bs[kv + 3][row] = vb.w;
        }
        __syncthreads();
        #pragma unroll
        for (int kk = 0; kk < 16; kk++) {
            float a[8], bv[8];
            #pragma unroll
            for (int i = 0; i < 8; i++) a[i] = As[kk][ty * 8 + i];
            #pragma unroll
            for (int j = 0; j < 8; j++) bv[j] = Bs[kk][tx * 8 + j];
            #pragma unroll
            for (int i = 0; i < 8; i++)
                #pragma unroll
                for (int j = 0; j < 8; j++)
                    acc[i][j] = fmaf(a[i], bv[j], acc[i][j]);
        }
        __syncthreads();
    }

    float bias[8];
    #pragma unroll
    for (int j = 0; j < 8; j++) {
        int n = n0 + tx * 8 + j;
        bias[j] = bi[n] + bh[n];
    }
    #pragma unroll
    for (int i = 0; i < 8; i++) {
        int m = m0 + ty * 8 + i;
        int s = m >> 6;
        int b = m & 63;
        float* dst = &g_xp[s][b][dir * GG + n0 + tx * 8];
        float4 v0, v1;
        v0.x = acc[i][0] + bias[0]; v0.y = acc[i][1] + bias[1];
        v0.z = acc[i][2] + bias[2]; v0.w = acc[i][3] + bias[3];
        v1.x = acc[i][4] + bias[4]; v1.y = acc[i][5] + bias[5];
        v1.z = acc[i][6] + bias[6]; v1.w = acc[i][7] + bias[7];
        *reinterpret_cast<float4*>(dst)     = v0;
        *reinterpret_cast<float4*>(dst + 4) = v1;
    }
}

// ---------------------------------------------------------------------------
// One LSTM step, both directions (grid = (64, 2)).
// Block (u0 = blockIdx.x*16): owns hidden units u0..u0+15 of its direction.
// Phase 1: gates[64 b][64 cols] where col = q*16 + u, q in {i,f,g,o};
//          gates = h(prev) @ w_hhᵀ  (K=1024, SMEM-staged, 4x4 micro-tiles)
// Phase 2: add xp, apply nonlinearity, update c/h, write output.
// ---------------------------------------------------------------------------
#define NU 16
#define SBK 32

__global__ __launch_bounds__(256) void lstm_step(
    int t,
    const float* __restrict__ whh_fw,
    const float* __restrict__ whh_bw,
    float* __restrict__ out)
{
    const int dir = blockIdx.y;
    const float* __restrict__ whh = dir ? whh_bw : whh_fw;
    const int u0 = blockIdx.x * NU;
    const int rd = t & 1;       // read parity
    const int wr = rd ^ 1;      // write parity

    __shared__ float Hs[SBK][64];
    __shared__ float Ws[SBK][64];
    __shared__ float Gsm[64][65];

    const int tid = threadIdx.x;
    const int tx = tid & 15;
    const int ty = tid >> 4;

    float acc[4][4];
    #pragma unroll
    for (int i = 0; i < 4; i++)
        #pragma unroll
        for (int j = 0; j < 4; j++) acc[i][j] = 0.f;

    for (int k0 = 0; k0 < HH; k0 += SBK) {
        #pragma unroll
        for (int it = 0; it < 2; it++) {
            int idx = tid + it * 256;     // 0..511
            int row = idx >> 3;           // 0..63
            int kv  = (idx & 7) * 4;      // 0..28
            float4 hv = *reinterpret_cast<const float4*>(
                &g_h[rd][dir][row][k0 + kv]);
            Hs[kv + 0][row] = hv.x; Hs[kv + 1][row] = hv.y;
            Hs[kv + 2][row] = hv.z; Hs[kv + 3][row] = hv.w;
            // local W row 'row' -> gate row (row/16)*H + u0 + (row%16)
            int gq = (row >> 4) * HH + u0 + (row & 15);
            float4 wv = *reinterpret_cast<const float4*>(
                whh + (size_t)gq * HH + k0 + kv);
            Ws[kv + 0][row] = wv.x; Ws[kv + 1][row] = wv.y;
            Ws[kv + 2][row] = wv.z; Ws[kv + 3][row] = wv.w;
        }
        __syncthreads();
        #pragma unroll
        for (int kk = 0; kk < SBK; kk++) {
            float a[4], wv[4];
            #pragma unroll
            for (int i = 0; i < 4; i++) a[i] = Hs[kk][ty * 4 + i];
            #pragma unroll
            for (int j = 0; j < 4; j++) wv[j] = Ws[kk][tx * 4 + j];
            #pragma unroll
            for (int i = 0; i < 4; i++)
                #pragma unroll
                for (int j = 0; j < 4; j++)
                    acc[i][j] = fmaf(a[i], wv[j], acc[i][j]);
        }
        __syncthreads();
    }

    #pragma unroll
    for (int i = 0; i < 4; i++)
        #pragma unroll
        for (int j = 0; j < 4; j++)
            Gsm[ty * 4 + i][tx * 4 + j] = acc[i][j];
    __syncthreads();

    const int s = dir ? (TT - 1 - t) : t;
    for (int p = tid; p < 64 * NU; p += 256) {
        int b = p & 63;
        int u = p >> 6;                 // 0..15
        const float* xpb = &g_xp[s][b][dir * GG];
        float iv = Gsm[b][ 0 + u] + xpb[0 * HH + u0 + u];
        float fv = Gsm[b][16 + u] + xpb[1 * HH + u0 + u];
        float gv = Gsm[b][32 + u] + xpb[2 * HH + u0 + u];
        float ov = Gsm[b][48 + u] + xpb[3 * HH + u0 + u];

        float ig = 1.f / (1.f + __expf(-iv));
        float fg = 1.f / (1.f + __expf(-fv));
        float og = 1.f / (1.f + __expf(-ov));
        float c_old = g_c[dir][b][u0 + u];
        float cn = fg * c_old + ig * tanhf(gv);
        float hn = og * tanhf(cn);

        g_c[dir][b][u0 + u]     = cn;
        g_h[wr][dir][b][u0 + u] = hn;
        out[((size_t)b * TT + t) * (2 * HH) + dir * HH + u0 + u] = hn;
    }
}

// ---------------------------------------------------------------------------
// Tails: h_fw, c_fw, h_bw, c_bw after the outputs tensor.
// Final h lives in parity (T & 1) == 0.
// ---------------------------------------------------------------------------
__global__ void write_tails(float* __restrict__ out) {
    const size_t base = (size_t)BB * TT * 2 * HH;
    int idx = blockIdx.x * blockDim.x + threadIdx.x;
    if (idx < BB * HH) {
        int b = idx / HH;
        int j = idx % HH;
        out[base + 0 * BB * HH + idx] = g_h[0][0][b][j];  // h_fw
        out[base + 1 * BB * HH + idx] = g_c[0][b][j];     // c_fw
        out[base + 2 * BB * HH + idx] = g_h[0][1][b][j];  // h_bw
        out[base + 3 * BB * HH + idx] = g_c[1][b][j];     // c_bw
    }
}

// ---------------------------------------------------------------------------
extern "C" void kernel_launch(void* const* d_in, const int* in_sizes, int n_in,
                              void* d_out, int out_size)
{
    const float* x       = (const float*)d_in[0];
    const float* w_ih_fw = (const float*)d_in[1];
    const float* w_hh_fw = (const float*)d_in[2];
    const float* b_ih_fw = (const float*)d_in[3];
    const float* b_hh_fw = (const float*)d_in[4];
    const float* w_ih_bw = (const float*)d_in[5];
    const float* w_hh_bw = (const float*)d_in[6];
    const float* b_ih_bw = (const float*)d_in[7];
    const float* b_hh_bw = (const float*)d_in[8];
    float* out = (float*)d_out;

    init_state<<<2048, 256>>>();

    // xp for both directions: grid (N/128, M/128, dirs)
    xp_gemm<<<dim3(32, 256, 2), 256>>>(x, w_ih_fw, w_ih_bw,
                                       b_ih_fw, b_hh_fw, b_ih_bw, b_hh_bw);

    for (int t = 0; t < TT; t++)
        lstm_step<<<dim3(64, 2), 256>>>(t, w_hh_fw, w_hh_bw, out);

    write_tails<<<(BB * HH + 255) / 256, 256>>>(out);
}

// round 5
// speedup vs baseline: 2.0438x; 2.0438x over previous
#include <cuda_runtime.h>

// Problem constants
#define BB 64
#define TT 512
#define II 512
#define HH 1024
#define GG 4096   // 4*H
#define CH 32     // k per smem chunk
#define NCH (HH / CH)
#define NBLK 128
#define NTHR 128

// ---------------------------------------------------------------------------
// Device scratch (static — no allocations allowed)
// ---------------------------------------------------------------------------
__device__ float g_xp[TT][BB][2 * GG];    // 1 GB: input projection + biases, time s
__device__ float g_hT[2][2][HH][BB];      // [parity][dir][unit(k)][b]  (transposed h)
__device__ float g_c[2][BB][HH];          // [dir][b][u]
__device__ float g_wT[2][HH][GG];         // w_hh transposed + column-permuted
__device__ unsigned g_bar;                // grid barrier arrival counter

// ---------------------------------------------------------------------------
// FFMA2 helpers (packed f32x2 — 2x fp32 FMA throughput on sm_103a)
// ---------------------------------------------------------------------------
__device__ __forceinline__ unsigned long long pk2(float lo, float hi) {
    unsigned long long r;
    asm("mov.b64 %0, {%1, %2};" : "=l"(r) : "f"(lo), "f"(hi));
    return r;
}
__device__ __forceinline__ void fma2(unsigned long long& d,
                                     unsigned long long a, unsigned long long b) {
    asm("fma.rn.f32x2 %0, %1, %2, %0;" : "+l"(d) : "l"(a), "l"(b));
}
__device__ __forceinline__ float2 upk(unsigned long long v) {
    float2 f;
    asm("mov.b64 {%0, %1}, %2;" : "=f"(f.x), "=f"(f.y) : "l"(v));
    return f;
}
__device__ __forceinline__ float sigm(float x) {
    return 1.f / (1.f + __expf(-x));
}

// ---------------------------------------------------------------------------
// Reset state + barrier (runs every launch — determinism across replays)
// ---------------------------------------------------------------------------
__global__ void init_state() {
    int idx = blockIdx.x * blockDim.x + threadIdx.x;
    const int n_h = 2 * 2 * HH * BB;     // 262144
    const int n_c = 2 * BB * HH;         // 131072
    if (idx < n_h) ((float*)g_hT)[idx] = 0.f;
    if (idx < n_c) ((float*)g_c)[idx] = 0.f;
    if (idx == 0) g_bar = 0u;
}

// ---------------------------------------------------------------------------
// One-time w_hh transpose into g_wT[dir][k][pc]:
//   pc = ublock*64 + q*16 + u  <->  src_row = q*H + ublock*16 + u
// so block 'ublk' reads a contiguous 64-col slice with rows k-major.
// ---------------------------------------------------------------------------
__global__ void transpose_w(const float* __restrict__ fw,
                            const float* __restrict__ bw) {
    int idx = blockIdx.x * blockDim.x + threadIdx.x;
    if (idx >= 2 * HH * GG) return;
    int dir = idx / (HH * GG);
    int rem = idx % (HH * GG);
    int k  = rem / GG;
    int pc = rem % GG;
    int ublock = pc >> 6;
    int r2 = pc & 63;
    int q = r2 >> 4;
    int u = r2 & 15;
    int src_row = q * HH + ublock * 16 + u;
    const float* w = dir ? bw : fw;
    g_wT[dir][k][pc] = w[(size_t)src_row * HH + k];
}

// ---------------------------------------------------------------------------
// xp GEMM (unchanged, known-good): g_xp[s][b][dir*4096+n] = x@w_ih^T + biases
// ---------------------------------------------------------------------------
__global__ __launch_bounds__(256) void xp_gemm(
    const float* __restrict__ x,
    const float* __restrict__ w_fw, const float* __restrict__ w_bw,
    const float* __restrict__ bih_fw, const float* __restrict__ bhh_fw,
    const float* __restrict__ bih_bw, const float* __restrict__ bhh_bw)
{
    const int dir = blockIdx.z;
    const float* __restrict__ w  = dir ? w_bw  : w_fw;
    const float* __restrict__ bi = dir ? bih_bw : bih_fw;
    const float* __restrict__ bh = dir ? bhh_bw : bhh_fw;
    const int n0 = blockIdx.x * 128;
    const int m0 = blockIdx.y * 128;

    __shared__ float As[16][128];
    __shared__ float Bs[16][128];

    const int tid = threadIdx.x;
    const int tx = tid & 15;
    const int ty = tid >> 4;

    float acc[8][8];
    #pragma unroll
    for (int i = 0; i < 8; i++)
        #pragma unroll
        for (int j = 0; j < 8; j++) acc[i][j] = 0.f;

    for (int k0 = 0; k0 < II; k0 += 16) {
        #pragma unroll
        for (int it = 0; it < 2; it++) {
            int idx = tid + it * 256;
            int row = idx >> 2;
            int kv  = (idx & 3) * 4;
            int m = m0 + row;
            int s = m >> 6;
            int b = m & 63;
            float4 va = *reinterpret_cast<const float4*>(
                x + ((size_t)b * TT + s) * II + k0 + kv);
            As[kv + 0][row] = va.x; As[kv + 1][row] = va.y;
            As[kv + 2][row] = va.z; As[kv + 3][row] = va.w;
            float4 vb = *reinterpret_cast<const float4*>(
                w + (size_t)(n0 + row) * II + k0 + kv);
            Bs[kv + 0][row] = vb.x; Bs[kv + 1][row] = vb.y;
            Bs[kv + 2][row] = vb.z; Bs[kv + 3][row] = vb.w;
        }
        __syncthreads();
        #pragma unroll
        for (int kk = 0; kk < 16; kk++) {
            float a[8], bv[8];
            #pragma unroll
            for (int i = 0; i < 8; i++) a[i] = As[kk][ty * 8 + i];
            #pragma unroll
            for (int j = 0; j < 8; j++) bv[j] = Bs[kk][tx * 8 + j];
            #pragma unroll
            for (int i = 0; i < 8; i++)
                #pragma unroll
                for (int j = 0; j < 8; j++)
                    acc[i][j] = fmaf(a[i], bv[j], acc[i][j]);
        }
        __syncthreads();
    }

    float bias[8];
    #pragma unroll
    for (int j = 0; j < 8; j++) {
        int n = n0 + tx * 8 + j;
        bias[j] = bi[n] + bh[n];
    }
    #pragma unroll
    for (int i = 0; i < 8; i++) {
        int m = m0 + ty * 8 + i;
        int s = m >> 6;
        int b = m & 63;
        float* dst = &g_xp[s][b][dir * GG + n0 + tx * 8];
        float4 v0, v1;
        v0.x = acc[i][0] + bias[0]; v0.y = acc[i][1] + bias[1];
        v0.z = acc[i][2] + bias[2]; v0.w = acc[i][3] + bias[3];
        v1.x = acc[i][4] + bias[4]; v1.y = acc[i][5] + bias[5];
        v1.z = acc[i][6] + bias[6]; v1.w = acc[i][7] + bias[7];
        *reinterpret_cast<float4*>(dst)     = v0;
        *reinterpret_cast<float4*>(dst + 4) = v1;
    }
}

// ---------------------------------------------------------------------------
// Persistent recurrence kernel: 128 blocks (all co-resident) x 128 threads.
// Block = (dir, 16 hidden units): 64x64 gate tile (64 batch x [4 gates x 16 u]),
// K = 1024, FFMA2 microkernel (4 batch x 8 col per thread), one grid barrier
// per timestep.
// ---------------------------------------------------------------------------
__global__ __launch_bounds__(NTHR, 1) void lstm_persist(float* __restrict__ out)
{
    const int bid = blockIdx.x;
    const int dir = bid >> 6;
    const int ublk = bid & 63;
    const int u0 = ublk * 16;
    const int c0w = ublk * 64;
    const int tid = threadIdx.x;

    __shared__ __align__(16) float Hs[2][CH][68];
    __shared__ __align__(16) float Ws[2][CH][68];

    // staging map: 2 k-rows per warp pass, 16B per lane
    const int ld_k4 = tid >> 4;   // 0..7
    const int ld_f  = tid & 15;   // 0..15
    // compute map: 8 col-groups x 16 batch-groups
    const int cg = tid & 7;       // cols cg*8 .. +7
    const int ty = tid >> 3;      // batches ty*4 .. +3
    // cell map: 2 threads per batch
    const int cb   = tid >> 1;    // batch 0..63
    const int ub   = (tid & 1) * 8;  // unit sub-range (8 units)

    for (int t = 0; t < TT; t++) {
        const int rd = t & 1;
        const int wr = rd ^ 1;

        unsigned long long acc[2][8];
        #pragma unroll
        for (int i = 0; i < 2; i++)
            #pragma unroll
            for (int j = 0; j < 8; j++) acc[i][j] = 0ULL;

        float4 hreg[4], wreg[4];

        // prologue: stage chunk 0
        #pragma unroll
        for (int r = 0; r < 4; r++) {
            int kk = ld_k4 * 4 + r;
            hreg[r] = __ldcg((const float4*)&g_hT[rd][dir][kk][ld_f * 4]);
            wreg[r] = *(const float4*)&g_wT[dir][kk][c0w + ld_f * 4];
        }
        #pragma unroll
        for (int r = 0; r < 4; r++) {
            int kk = ld_k4 * 4 + r;
            *(float4*)&Hs[0][kk][ld_f * 4] = hreg[r];
            *(float4*)&Ws[0][kk][ld_f * 4] = wreg[r];
        }
        __syncthreads();

        for (int c = 0; c < NCH; c++) {
            const int p = c & 1;
            if (c + 1 < NCH) {
                int k0 = (c + 1) * CH;
                #pragma unroll
                for (int r = 0; r < 4; r++) {
                    int kk = k0 + ld_k4 * 4 + r;
                    hreg[r] = __ldcg((const float4*)&g_hT[rd][dir][kk][ld_f * 4]);
                    wreg[r] = *(const float4*)&g_wT[dir][kk][c0w + ld_f * 4];
                }
            }
            #pragma unroll
            for (int k = 0; k < CH; k++) {
                ulonglong2 av = *(const ulonglong2*)&Hs[p][k][ty * 4];
                float4 w0 = *(const float4*)&Ws[p][k][cg * 8];
                float4 w1 = *(const float4*)&Ws[p][k][cg * 8 + 4];
                unsigned long long bp;
                bp = pk2(w0.x, w0.x); fma2(acc[0][0], av.x, bp); fma2(acc[1][0], av.y, bp);
                bp = pk2(w0.y, w0.y); fma2(acc[0][1], av.x, bp); fma2(acc[1][1], av.y, bp);
                bp = pk2(w0.z, w0.z); fma2(acc[0][2], av.x, bp); fma2(acc[1][2], av.y, bp);
                bp = pk2(w0.w, w0.w); fma2(acc[0][3], av.x, bp); fma2(acc[1][3], av.y, bp);
                bp = pk2(w1.x, w1.x); fma2(acc[0][4], av.x, bp); fma2(acc[1][4], av.y, bp);
                bp = pk2(w1.y, w1.y); fma2(acc[0][5], av.x, bp); fma2(acc[1][5], av.y, bp);
                bp = pk2(w1.z, w1.z); fma2(acc[0][6], av.x, bp); fma2(acc[1][6], av.y, bp);
                bp = pk2(w1.w, w1.w); fma2(acc[0][7], av.x, bp); fma2(acc[1][7], av.y, bp);
            }
            if (c + 1 < NCH) {
                __syncthreads();
                const int pn = p ^ 1;
                #pragma unroll
                for (int r = 0; r < 4; r++) {
                    int kk = ld_k4 * 4 + r;
                    *(float4*)&Hs[pn][kk][ld_f * 4] = hreg[r];
                    *(float4*)&Ws[pn][kk][ld_f * 4] = wreg[r];
                }
                __syncthreads();
            }
        }

        // gate tile -> smem (alias Hs; all GEMM reads of Hs are done)
        __syncthreads();
        float (*Gsm)[68] = (float (*)[68]) & Hs[0][0][0];
        #pragma unroll
        for (int rr = 0; rr < 4; rr++) {
            float vals[8];
            #pragma unroll
            for (int j = 0; j < 8; j++) {
                float2 v = upk(acc[rr >> 1][j]);
                vals[j] = (rr & 1) ? v.y : v.x;
            }
            *(float4*)&Gsm[ty * 4 + rr][cg * 8] =
                make_float4(vals[0], vals[1], vals[2], vals[3]);
            *(float4*)&Gsm[ty * 4 + rr][cg * 8 + 4] =
                make_float4(vals[4], vals[5], vals[6], vals[7]);
        }
        __syncthreads();

        // cell update: thread -> (batch cb, units u0+ub .. +7)
        {
            const int s = dir ? (TT - 1 - t) : t;
            const float* xpb = &g_xp[s][cb][dir * GG];
            float gq[4][8];
            #pragma unroll
            for (int q = 0; q < 4; q++) {
                float4 x0 = __ldg((const float4*)&xpb[q * HH + u0 + ub]);
                float4 x1 = __ldg((const float4*)&xpb[q * HH + u0 + ub + 4]);
                float4 s0 = *(const float4*)&Gsm[cb][q * 16 + ub];
                float4 s1 = *(const float4*)&Gsm[cb][q * 16 + ub + 4];
                gq[q][0] = x0.x + s0.x; gq[q][1] = x0.y + s0.y;
                gq[q][2] = x0.z + s0.z; gq[q][3] = x0.w + s0.w;
                gq[q][4] = x1.x + s1.x; gq[q][5] = x1.y + s1.y;
                gq[q][6] = x1.z + s1.z; gq[q][7] = x1.w + s1.w;
            }
            float4 cv0 = __ldcg((const float4*)&g_c[dir][cb][u0 + ub]);
            float4 cv1 = __ldcg((const float4*)&g_c[dir][cb][u0 + ub + 4]);
            float cold[8] = {cv0.x, cv0.y, cv0.z, cv0.w, cv1.x, cv1.y, cv1.z, cv1.w};
            float hn[8], cn[8];
            #pragma unroll
            for (int j = 0; j < 8; j++) {
                float ig = sigm(gq[0][j]);
                float fg = sigm(gq[1][j]);
                float og = sigm(gq[3][j]);
                cn[j] = fg * cold[j] + ig * tanhf(gq[2][j]);
                hn[j] = og * tanhf(cn[j]);
            }
            __stcg((float4*)&g_c[dir][cb][u0 + ub],
                   make_float4(cn[0], cn[1], cn[2], cn[3]));
            __stcg((float4*)&g_c[dir][cb][u0 + ub + 4],
                   make_float4(cn[4], cn[5], cn[6], cn[7]));
            #pragma unroll
            for (int j = 0; j < 8; j++)
                __stcg(&g_hT[wr][dir][u0 + ub + j][cb], hn[j]);
            float* op = &out[((size_t)cb * TT + t) * (2 * HH) + dir * HH + u0 + ub];
            *(float4*)op       = make_float4(hn[0], hn[1], hn[2], hn[3]);
            *(float4*)(op + 4) = make_float4(hn[4], hn[5], hn[6], hn[7]);
        }

        // grid barrier: all h[wr] writes visible before anyone starts step t+1
        __syncthreads();
        if (tid == 0) {
            __threadfence();
            atomicAdd(&g_bar, 1u);
            const unsigned target = (unsigned)(t + 1) * NBLK;
            while (*(volatile unsigned*)&g_bar < target) { }
            __threadfence();
        }
        __syncthreads();
    }
}

// ---------------------------------------------------------------------------
// Tails: h_fw, c_fw, h_bw, c_bw after outputs. Final h parity = 0.
// ---------------------------------------------------------------------------
__global__ void write_tails(float* __restrict__ out) {
    const size_t base = (size_t)BB * TT * 2 * HH;
    int idx = blockIdx.x * blockDim.x + threadIdx.x;
    if (idx < BB * HH) {
        int b = idx / HH;
        int j = idx % HH;
        out[base + 0 * BB * HH + idx] = g_hT[0][0][j][b];  // h_fw
        out[base + 1 * BB * HH + idx] = g_c[0][b][j];      // c_fw
        out[base + 2 * BB * HH + idx] = g_hT[0][1][j][b];  // h_bw
        out[base + 3 * BB * HH + idx] = g_c[1][b][j];      // c_bw
    }
}

// ---------------------------------------------------------------------------
extern "C" void kernel_launch(void* const* d_in, const int* in_sizes, int n_in,
                              void* d_out, int out_size)
{
    const float* x       = (const float*)d_in[0];
    const float* w_ih_fw = (const float*)d_in[1];
    const float* w_hh_fw = (const float*)d_in[2];
    const float* b_ih_fw = (const float*)d_in[3];
    const float* b_hh_fw = (const float*)d_in[4];
    const float* w_ih_bw = (const float*)d_in[5];
    const float* w_hh_bw = (const float*)d_in[6];
    const float* b_ih_bw = (const float*)d_in[7];
    const float* b_hh_bw = (const float*)d_in[8];
    float* out = (float*)d_out;

    init_state<<<1024, 256>>>();
    transpose_w<<<(2 * HH * GG + 255) / 256, 256>>>(w_hh_fw, w_hh_bw);
    xp_gemm<<<dim3(32, 256, 2), 256>>>(x, w_ih_fw, w_ih_bw,
                                       b_ih_fw, b_hh_fw, b_ih_bw, b_hh_bw);
    lstm_persist<<<NBLK, NTHR>>>(out);
    write_tails<<<(BB * HH + 255) / 256, 256>>>(out);
}